// round 3
// baseline (speedup 1.0000x reference)
#include <cuda_runtime.h>
#include <math.h>

#define Tn   512
#define Bn   64
#define Hn   512
#define G4   2048
#define NOUT 128
#define NCTA_LSTM 128

__device__ float g_xw[(size_t)2 * Tn * Bn * G4];
__device__ float g_out0[(size_t)Tn * Bn * 2 * Hn];
__device__ float g_out1[(size_t)Tn * Bn * 2 * Hn];
__device__ float g_hT[2 * 2 * Hn * Bn];
__device__ float g_attn[Bn * Tn];
__device__ unsigned g_bar;

__device__ __forceinline__ unsigned long long pk2(float lo, float hi) {
    unsigned long long r;
    asm("mov.b64 %0, {%1, %2};" : "=l"(r) : "f"(lo), "f"(hi));
    return r;
}
__device__ __forceinline__ void fma2(unsigned long long& d, unsigned long long a, unsigned long long b) {
    asm("fma.rn.f32x2 %0, %1, %2, %0;" : "+l"(d) : "l"(a), "l"(b));
}
__device__ __forceinline__ float2 upk2(unsigned long long v) {
    float2 r;
    asm("mov.b64 {%0, %1}, %2;" : "=f"(r.x), "=f"(r.y) : "l"(v));
    return r;
}

// ============ GEMM: C[dir][m][n] = X[m][:] . W[dir][n][:] + b[dir][n] ============
#define GBM 128
#define GBN 128
#define GBK 16

__global__ __launch_bounds__(256, 2)
void gemm_xw_kernel(const float* __restrict__ X, const float* __restrict__ W,
                    const float* __restrict__ bias, float* __restrict__ C, int K) {
    const int N = G4, M = Tn * Bn;
    const int dir = blockIdx.z;
    const float* Wd = W + (size_t)dir * N * K;
    const float* bd = bias + (size_t)dir * N;
    float* Cd = C + (size_t)dir * M * N;

    __shared__ __align__(16) float As[GBK][GBM + 4];
    __shared__ __align__(16) float Bs[GBK][GBN + 4];

    const int tid = threadIdx.x;
    const int m0 = blockIdx.y * GBM;
    const int n0 = blockIdx.x * GBN;
    const int tx = tid & 15, ty = tid >> 4;
    const int lrow = tid >> 1;
    const int lk = (tid & 1) * 8;

    unsigned long long acc[8][4];
#pragma unroll
    for (int i = 0; i < 8; i++)
#pragma unroll
        for (int j = 0; j < 4; j++) acc[i][j] = 0ULL;

#pragma unroll 1
    for (int kt = 0; kt < K; kt += GBK) {
        float4 a0 = *(const float4*)(X + (size_t)(m0 + lrow) * K + kt + lk);
        float4 a1 = *(const float4*)(X + (size_t)(m0 + lrow) * K + kt + lk + 4);
        float4 b0 = *(const float4*)(Wd + (size_t)(n0 + lrow) * K + kt + lk);
        float4 b1 = *(const float4*)(Wd + (size_t)(n0 + lrow) * K + kt + lk + 4);
        __syncthreads();
        As[lk+0][lrow]=a0.x; As[lk+1][lrow]=a0.y; As[lk+2][lrow]=a0.z; As[lk+3][lrow]=a0.w;
        As[lk+4][lrow]=a1.x; As[lk+5][lrow]=a1.y; As[lk+6][lrow]=a1.z; As[lk+7][lrow]=a1.w;
        Bs[lk+0][lrow]=b0.x; Bs[lk+1][lrow]=b0.y; Bs[lk+2][lrow]=b0.z; Bs[lk+3][lrow]=b0.w;
        Bs[lk+4][lrow]=b1.x; Bs[lk+5][lrow]=b1.y; Bs[lk+6][lrow]=b1.z; Bs[lk+7][lrow]=b1.w;
        __syncthreads();
#pragma unroll
        for (int k = 0; k < GBK; k++) {
            float4 af0 = *(const float4*)&As[k][ty * 8];
            float4 af1 = *(const float4*)&As[k][ty * 8 + 4];
            ulonglong2 bp0 = *(const ulonglong2*)&Bs[k][tx * 8];
            ulonglong2 bp1 = *(const ulonglong2*)&Bs[k][tx * 8 + 4];
            float a[8] = {af0.x, af0.y, af0.z, af0.w, af1.x, af1.y, af1.z, af1.w};
            unsigned long long b2[4] = {bp0.x, bp0.y, bp1.x, bp1.y};
#pragma unroll
            for (int i = 0; i < 8; i++) {
                unsigned long long ad = pk2(a[i], a[i]);
                fma2(acc[i][0], ad, b2[0]);
                fma2(acc[i][1], ad, b2[1]);
                fma2(acc[i][2], ad, b2[2]);
                fma2(acc[i][3], ad, b2[3]);
            }
        }
    }
#pragma unroll
    for (int i = 0; i < 8; i++) {
        float* cp = Cd + (size_t)(m0 + ty * 8 + i) * G4 + n0 + tx * 8;
#pragma unroll
        for (int j = 0; j < 4; j++) {
            float2 v = upk2(acc[i][j]);
            v.x += bd[n0 + tx * 8 + 2 * j];
            v.y += bd[n0 + tx * 8 + 2 * j + 1];
            *(float2*)(cp + 2 * j) = v;
        }
    }
}

// ============ init: reset barrier + zero h state ============
__global__ void init_kernel() {
    int i = blockIdx.x * blockDim.x + threadIdx.x;
    if (i == 0) g_bar = 0u;
    for (int j = i; j < 2 * 2 * Hn * Bn; j += gridDim.x * blockDim.x) g_hT[j] = 0.f;
}

// ============ persistent bidirectional LSTM layer ============
__global__ __launch_bounds__(256)
void lstm_kernel(const float* __restrict__ xw, const float* __restrict__ Whh,
                 float* __restrict__ out) {
    extern __shared__ float sm[];
    float* sW = sm;                 // [32][513]
    float* sH = sW + 32 * 513;      // [32][72]
    float* sG = sH + 32 * 72;       // [32][66]
    float* sC = sG + 32 * 66;       // [8][64]

    const int tid = threadIdx.x;
    const int dir = blockIdx.x >> 6;
    const int u0 = (blockIdx.x & 63) << 3;

    for (int i = tid; i < 32 * 512; i += 256) {
        int r = i >> 9, k = i & 511;
        int gb = r >> 3, uu = u0 + (r & 7);
        sW[r * 513 + k] = Whh[((size_t)dir * G4 + gb * Hn + uu) * Hn + k];
    }
    for (int i = tid; i < 512; i += 256) sC[i] = 0.f;
    __syncthreads();

    const int r = tid & 31;
    const int b0 = (tid >> 5) << 3;
    const int xb = tid >> 2;
    const int xgb = tid & 3;
    const int ck = tid >> 4;
    const int cb = (tid & 15) << 2;
    const int pb = tid & 63;
    const int pu = tid >> 6;

#pragma unroll 1
    for (int s = 0; s < Tn; s++) {
        const int t = dir ? (Tn - 1 - s) : s;
        const float* hin = g_hT + (((size_t)(s & 1) * 2 + dir) << 15);

        {   // stage xw[dir][t][b][our 32 gate rows]
            const float* xp = xw + (((size_t)dir * Tn + t) * Bn + xb) * G4 + xgb * Hn + u0;
            float4 x0 = *(const float4*)xp;
            float4 x1 = *(const float4*)(xp + 4);
            float xv[8] = {x0.x, x0.y, x0.z, x0.w, x1.x, x1.y, x1.z, x1.w};
#pragma unroll
            for (int j = 0; j < 8; j++) sG[(xgb * 8 + j) * 66 + xb] = xv[j];
        }
        __syncthreads();

        unsigned long long acc0 = pk2(sG[r * 66 + b0 + 0], sG[r * 66 + b0 + 1]);
        unsigned long long acc1 = pk2(sG[r * 66 + b0 + 2], sG[r * 66 + b0 + 3]);
        unsigned long long acc2 = pk2(sG[r * 66 + b0 + 4], sG[r * 66 + b0 + 5]);
        unsigned long long acc3 = pk2(sG[r * 66 + b0 + 6], sG[r * 66 + b0 + 7]);

#pragma unroll 1
        for (int kc = 0; kc < Hn; kc += 32) {
            float4 va = __ldcg((const float4*)(hin + (size_t)(kc + ck) * Bn + cb));
            float4 vb = __ldcg((const float4*)(hin + (size_t)(kc + ck + 16) * Bn + cb));
            __syncthreads();
            *(float4*)&sH[ck * 72 + cb] = va;
            *(float4*)&sH[(ck + 16) * 72 + cb] = vb;
            __syncthreads();
#pragma unroll 8
            for (int k = 0; k < 32; k++) {
                float w = sW[r * 513 + kc + k];
                unsigned long long w2 = pk2(w, w);
                ulonglong2 h01 = *(const ulonglong2*)&sH[k * 72 + b0];
                ulonglong2 h23 = *(const ulonglong2*)&sH[k * 72 + b0 + 4];
                fma2(acc0, h01.x, w2);
                fma2(acc1, h01.y, w2);
                fma2(acc2, h23.x, w2);
                fma2(acc3, h23.y, w2);
            }
        }

        {
            float2 p0 = upk2(acc0), p1 = upk2(acc1), p2 = upk2(acc2), p3 = upk2(acc3);
            sG[r*66+b0+0]=p0.x; sG[r*66+b0+1]=p0.y; sG[r*66+b0+2]=p1.x; sG[r*66+b0+3]=p1.y;
            sG[r*66+b0+4]=p2.x; sG[r*66+b0+5]=p2.y; sG[r*66+b0+6]=p3.x; sG[r*66+b0+7]=p3.y;
        }
        __syncthreads();

        float* hTout = g_hT + (((size_t)((s + 1) & 1) * 2 + dir) << 15);
#pragma unroll
        for (int hh = 0; hh < 2; hh++) {
            int ul = pu + hh * 4;
            float iv = sG[(0 * 8 + ul) * 66 + pb];
            float fv = sG[(1 * 8 + ul) * 66 + pb];
            float gv = sG[(2 * 8 + ul) * 66 + pb];
            float ov = sG[(3 * 8 + ul) * 66 + pb];
            iv = 1.f / (1.f + expf(-iv));
            fv = 1.f / (1.f + expf(-fv));
            gv = tanhf(gv);
            ov = 1.f / (1.f + expf(-ov));
            float c = fv * sC[ul * 64 + pb] + iv * gv;
            c = fminf(fmaxf(c, -100.f), 100.f);
            float hv = ov * tanhf(c);
            sC[ul * 64 + pb] = c;
            hTout[(size_t)(u0 + ul) * Bn + pb] = hv;
            out[((size_t)t * Bn + pb) * (2 * Hn) + dir * Hn + u0 + ul] = hv;
        }

        if (s < Tn - 1) {
            __threadfence();
            __syncthreads();
            if (tid == 0) {
                atomicAdd(&g_bar, 1u);
                unsigned target = (unsigned)NCTA_LSTM * (unsigned)(s + 1);
                while (*(volatile unsigned*)&g_bar < target) {}
            }
            __syncthreads();
        }
    }
}

// ============ attention logits + softmax (CTA per batch) ============
__global__ __launch_bounds__(512)
void attn_kernel(const float* __restrict__ h1, const float* __restrict__ Wa,
                 const float* __restrict__ ba, float* __restrict__ outp,
                 float* __restrict__ attn_sc) {
    __shared__ float sWa[Hn];
    __shared__ float red[Tn];
    const int b = blockIdx.x, t = threadIdx.x;
    sWa[t] = Wa[t];
    __syncthreads();

    const float* hp = h1 + ((size_t)t * Bn + b) * (2 * Hn);
    float acc = 0.f;
#pragma unroll 4
    for (int u = 0; u < Hn; u += 4) {
        float4 hf = *(const float4*)(hp + u);
        float4 hb = *(const float4*)(hp + Hn + u);
        float4 wv = *(const float4*)(sWa + u);
        acc += (hf.x + hb.x) * wv.x + (hf.y + hb.y) * wv.y +
               (hf.z + hb.z) * wv.z + (hf.w + hb.w) * wv.w;
    }
    float logit = acc + ba[0];

    red[t] = logit; __syncthreads();
    for (int st = 256; st > 0; st >>= 1) {
        if (t < st) red[t] = fmaxf(red[t], red[t + st]);
        __syncthreads();
    }
    float m = red[0]; __syncthreads();
    float e = expf(logit - m);
    red[t] = e; __syncthreads();
    for (int st = 256; st > 0; st >>= 1) {
        if (t < st) red[t] += red[t + st];
        __syncthreads();
    }
    float a = e / red[0];
    outp[Bn * NOUT + b * Tn + t] = a;
    attn_sc[b * Tn + t] = a;
}

// ============ attention pooling + head (CTA per batch) ============
__global__ __launch_bounds__(512)
void pool_kernel(const float* __restrict__ h1, const float* __restrict__ Wo,
                 const float* __restrict__ bo, const float* __restrict__ attn_sc,
                 float* __restrict__ outp) {
    __shared__ float sa[Tn];
    __shared__ float sp[Hn];
    const int b = blockIdx.x, u = threadIdx.x;
    sa[u] = attn_sc[b * Tn + u];
    __syncthreads();

    float p = 0.f;
#pragma unroll 1
    for (int t = 0; t < Tn; t++) {
        const float* hp = h1 + ((size_t)t * Bn + b) * (2 * Hn);
        p += (hp[u] + hp[Hn + u]) * sa[t];
    }
    sp[u] = p;
    __syncthreads();

    if (u < NOUT) {
        float s = bo[u];
        const float* wp = Wo + (size_t)u * Hn;
        for (int k = 0; k < Hn; k++) s += sp[k] * wp[k];
        outp[b * NOUT + u] = s;
    }
}

extern "C" void kernel_launch(void* const* d_in, const int* in_sizes, int n_in,
                              void* d_out, int out_size) {
    (void)in_sizes; (void)n_in; (void)out_size;
    const float* input = (const float*)d_in[0];
    const float* Wih0  = (const float*)d_in[1];
    const float* Whh0  = (const float*)d_in[2];
    const float* b0    = (const float*)d_in[3];
    const float* Wih1  = (const float*)d_in[4];
    const float* Whh1  = (const float*)d_in[5];
    const float* b1    = (const float*)d_in[6];
    const float* Wa    = (const float*)d_in[7];
    const float* ba    = (const float*)d_in[8];
    const float* Wo    = (const float*)d_in[9];
    const float* bo    = (const float*)d_in[10];
    float* outp = (float*)d_out;

    float *xw, *out0, *out1, *attn_sc;
    cudaGetSymbolAddress((void**)&xw, g_xw);
    cudaGetSymbolAddress((void**)&out0, g_out0);
    cudaGetSymbolAddress((void**)&out1, g_out1);
    cudaGetSymbolAddress((void**)&attn_sc, g_attn);

    const int lstm_smem = (32 * 513 + 32 * 72 + 32 * 66 + 512) * (int)sizeof(float);
    static int configured = 0;
    if (!configured) {
        cudaFuncSetAttribute(lstm_kernel, cudaFuncAttributeMaxDynamicSharedMemorySize, lstm_smem);
        configured = 1;
    }

    dim3 ggrid(G4 / GBN, (Tn * Bn) / GBM, 2);

    // layer 0
    gemm_xw_kernel<<<ggrid, 256>>>(input, Wih0, b0, xw, 256);
    init_kernel<<<64, 256>>>();
    lstm_kernel<<<NCTA_LSTM, 256, lstm_smem>>>(xw, Whh0, out0);

    // layer 1
    gemm_xw_kernel<<<ggrid, 256>>>(out0, Wih1, b1, xw, 1024);
    init_kernel<<<64, 256>>>();
    lstm_kernel<<<NCTA_LSTM, 256, lstm_smem>>>(xw, Whh1, out1);

    // attention + head
    attn_kernel<<<Bn, Tn>>>(out1, Wa, ba, outp, attn_sc);
    pool_kernel<<<Bn, Tn>>>(out1, Wo, bo, attn_sc, outp);
}